// round 1
// baseline (speedup 1.0000x reference)
#include <cuda_runtime.h>

#define M_ROWS   4096
#define N_COLS   50000
#define DD       64
#define MTILE    64
#define NTILE    64
#define NTILES_J 782                 // ceil(50000/64)
#define NPAD     (NTILES_J * NTILE)  // 50048

// Static device scratch (no allocations allowed in kernel_launch)
__device__ float g_ax[M_ROWS];                 // -0.5*L*||x_i||^2
__device__ float g_bx[NPAD];                   // -0.5*L*||X_j||^2 (pad = -1e30)
__device__ float g_part[NTILES_J * M_ROWS];    // per-(jtile,row) partial sums, 12.8 MB

__device__ __forceinline__ float fexp2(float v) {
    float r;
    asm("ex2.approx.ftz.f32 %0, %1;" : "=f"(r) : "f"(v));
    return r;
}

// ---------------------------------------------------------------------------
// Prep: per-row/col squared-norm constants with bandwidth folded in.
// t_ij = logit*log2e = c_ij*L + ax_i + bx_j, L = log2e/b^2
// ---------------------------------------------------------------------------
__global__ void gkd_prep(const float* __restrict__ x,
                         const float* __restrict__ X,
                         const float* __restrict__ bw) {
    int i = blockIdx.x * blockDim.x + threadIdx.x;
    float b = bw[0];
    float L = 1.4426950408889634f / (b * b);

    if (i < NPAD) {
        float v = -1e30f;  // padded columns contribute exp2(-inf)=0
        if (i < N_COLS) {
            const float4* p = (const float4*)(X + (size_t)i * DD);
            float s = 0.f;
            #pragma unroll
            for (int t = 0; t < DD / 4; t++) {
                float4 q = p[t];
                s += q.x * q.x + q.y * q.y + q.z * q.z + q.w * q.w;
            }
            v = -0.5f * L * s;
        }
        g_bx[i] = v;
    }
    if (i < M_ROWS) {
        const float4* p = (const float4*)(x + (size_t)i * DD);
        float s = 0.f;
        #pragma unroll
        for (int t = 0; t < DD / 4; t++) {
            float4 q = p[t];
            s += q.x * q.x + q.y * q.y + q.z * q.z + q.w * q.w;
        }
        g_ax[i] = -0.5f * L * s;
    }
}

// ---------------------------------------------------------------------------
// Main: 64x64 output tile per CTA, K=64 fully resident in smem.
// 128 threads, 8x4 microtile -> 32 FFMA per 3 LDS.128 (FFMA-bound).
// Epilogue: s_i += 2^(acc + bx_j), reduced across the 16 column-threads,
// written to a deterministic partial buffer.
// ---------------------------------------------------------------------------
__global__ __launch_bounds__(128)
void gkd_main(const float* __restrict__ x,
              const float* __restrict__ X,
              const float* __restrict__ bw) {
    // transposed tiles: [k][row], +4 pad -> only 4-way STS conflicts, f4-aligned rows
    __shared__ float xs[DD * (MTILE + 4)];
    __shared__ float Xs[DD * (NTILE + 4)];

    const int jt = blockIdx.x;
    const int it = blockIdx.y;
    const int j0 = jt * NTILE;
    const int i0 = it * MTILE;

    const float b = bw[0];
    const float L = 1.4426950408889634f / (b * b);

    const int tid  = threadIdx.x;
    const int lane = tid & 31;
    const int warp = tid >> 5;

    // Load x tile (64 rows x 64 k), transposed. Consecutive lanes = consecutive k.
    for (int r = warp; r < MTILE; r += 4) {
        const float* px = x + (size_t)(i0 + r) * DD;
        xs[lane * 68 + r]        = px[lane];
        xs[(lane + 32) * 68 + r] = px[lane + 32];
    }
    // Load X tile, scaled by L (folds log2e/b^2 into the MMA result).
    for (int r = warp; r < NTILE; r += 4) {
        int j = j0 + r;
        float v0 = 0.f, v1 = 0.f;
        if (j < N_COLS) {
            const float* pX = X + (size_t)j * DD;
            v0 = pX[lane] * L;
            v1 = pX[lane + 32] * L;
        }
        Xs[lane * 68 + r]        = v0;
        Xs[(lane + 32) * 68 + r] = v1;
    }
    __syncthreads();

    const int tx = tid & 15;   // column group: 4 cols
    const int ty = tid >> 4;   // row group: 8 rows

    float acc[8][4];
    #pragma unroll
    for (int r = 0; r < 8; r++)
        #pragma unroll
        for (int c = 0; c < 4; c++) acc[r][c] = 0.f;

    #pragma unroll 16
    for (int k = 0; k < DD; k++) {
        float4 a0 = *(const float4*)(xs + k * 68 + ty * 8);
        float4 a1 = *(const float4*)(xs + k * 68 + ty * 8 + 4);
        float4 bb = *(const float4*)(Xs + k * 68 + tx * 4);
        float av[8] = {a0.x, a0.y, a0.z, a0.w, a1.x, a1.y, a1.z, a1.w};
        float bv[4] = {bb.x, bb.y, bb.z, bb.w};
        #pragma unroll
        for (int r = 0; r < 8; r++)
            #pragma unroll
            for (int c = 0; c < 4; c++)
                acc[r][c] += av[r] * bv[c];
    }

    // Epilogue: exp2 + row partial sums
    float bxv[4];
    #pragma unroll
    for (int c = 0; c < 4; c++) bxv[c] = g_bx[j0 + tx * 4 + c];

    #pragma unroll
    for (int r = 0; r < 8; r++) {
        float s = fexp2(acc[r][0] + bxv[0]) + fexp2(acc[r][1] + bxv[1])
                + fexp2(acc[r][2] + bxv[2]) + fexp2(acc[r][3] + bxv[3]);
        // reduce across the 16 tx lanes (xor 8/4/2/1 stays inside each 16-group)
        s += __shfl_xor_sync(0xffffffffu, s, 8);
        s += __shfl_xor_sync(0xffffffffu, s, 4);
        s += __shfl_xor_sync(0xffffffffu, s, 2);
        s += __shfl_xor_sync(0xffffffffu, s, 1);
        if (tx == 0)
            g_part[(size_t)jt * M_ROWS + i0 + ty * 8 + r] = s;
    }
}

// ---------------------------------------------------------------------------
// Finalize: deterministic fixed-order reduction + log
// out_i = ln2*(ax_i + log2(sum_j 2^(u_ij))) + coeff
// ---------------------------------------------------------------------------
__global__ void gkd_finalize(float* __restrict__ out) {
    int i = blockIdx.x * blockDim.x + threadIdx.x;
    if (i >= M_ROWS) return;
    float s = 0.f;
    #pragma unroll 4
    for (int t = 0; t < NTILES_J; t++)
        s += g_part[(size_t)t * M_ROWS + i];
    // coeff = -(ln(50000) + 32*ln(2*pi)) = -69.63184440950933
    out[i] = 0.6931471805599453f * (g_ax[i] + log2f(s)) - 69.63184440950933f;
}

extern "C" void kernel_launch(void* const* d_in, const int* in_sizes, int n_in,
                              void* d_out, int out_size) {
    // Identify inputs by element count (robust to metadata ordering):
    // x: 4096*64 = 262144, X: 50000*64 = 3200000, bandwidth: 1
    const float* x  = nullptr;
    const float* X  = nullptr;
    const float* bw = nullptr;
    for (int i = 0; i < n_in; i++) {
        if (in_sizes[i] == M_ROWS * DD)      x  = (const float*)d_in[i];
        else if (in_sizes[i] == N_COLS * DD) X  = (const float*)d_in[i];
        else if (in_sizes[i] == 1)           bw = (const float*)d_in[i];
    }
    float* out = (float*)d_out;

    gkd_prep<<<(NPAD + 255) / 256, 256>>>(x, X, bw);

    dim3 grid(NTILES_J, M_ROWS / MTILE);   // 782 x 64 CTAs
    gkd_main<<<grid, 128>>>(x, X, bw);

    gkd_finalize<<<(M_ROWS + 255) / 256, 256>>>(out);
}

// round 9
// speedup vs baseline: 5.5471x; 5.5471x over previous
#include <cuda_runtime.h>
#include <cstdint>

#define M_ROWS   4096
#define N_COLS   50000
#define DD       64
#define CTA_M    128
#define CTA_N    128
#define N_NT     391                 // ceil(50000/128)
#define NPAD     (N_NT * CTA_N)      // 50048
#define SA       68                  // smem row stride in floats (64 + 4 pad)

// ---------------- static device storage (no runtime allocs) ----------------
__device__ __align__(16) float g_A[M_ROWS * DD];     // tf32(x * L)
__device__ __align__(16) float g_B[NPAD * DD];       // tf32(X), padded rows = 0
__device__ float g_ax[M_ROWS];                       // -L/2 * ||x_i||^2
__device__ float g_bx[NPAD];                         // -L/2 * ||X_j||^2 (pad -1e30)
__device__ float g_part[(size_t)N_NT * M_ROWS];      // per-(ntile,row) partials

// ---------------- helpers ----------------
__device__ __forceinline__ float fexp2(float v) {
    float r; asm("ex2.approx.ftz.f32 %0, %1;" : "=f"(r) : "f"(v)); return r;
}
__device__ __forceinline__ float tf32r(float v) {
    uint32_t r; asm("cvt.rna.tf32.f32 %0, %1;" : "=r"(r) : "f"(v));
    return __uint_as_float(r);
}
__device__ __forceinline__ void mma_tf32(float* c, const uint32_t* a, const uint32_t* b) {
    asm volatile("mma.sync.aligned.m16n8k8.row.col.f32.tf32.tf32.f32 "
                 "{%0,%1,%2,%3}, {%4,%5,%6,%7}, {%8,%9}, {%0,%1,%2,%3};"
                 : "+f"(c[0]), "+f"(c[1]), "+f"(c[2]), "+f"(c[3])
                 : "r"(a[0]), "r"(a[1]), "r"(a[2]), "r"(a[3]), "r"(b[0]), "r"(b[1]));
}

// ---------------------------------------------------------------------------
// Prep: tf32-rounded images + squared-norm constants. L = log2e / b^2.
//   exponent(t_ij) = L*(x_i.X_j) + ax_i + bx_j  (ax added at finalize)
// ---------------------------------------------------------------------------
__global__ void gkd_prep_x(const float* __restrict__ x, const float* __restrict__ bw) {
    int i = blockIdx.x * blockDim.x + threadIdx.x;
    if (i >= M_ROWS) return;
    float b = bw[0];
    float L = 1.4426950408889634f / (b * b);
    const float4* p = (const float4*)(x + (size_t)i * DD);
    float4* q = (float4*)(g_A + (size_t)i * DD);
    float s = 0.f;
    #pragma unroll
    for (int t = 0; t < DD / 4; t++) {
        float4 v = p[t];
        s += v.x * v.x + v.y * v.y + v.z * v.z + v.w * v.w;
        float4 o;
        o.x = tf32r(v.x * L); o.y = tf32r(v.y * L);
        o.z = tf32r(v.z * L); o.w = tf32r(v.w * L);
        q[t] = o;
    }
    g_ax[i] = -0.5f * L * s;
}

__global__ void gkd_prep_X(const float* __restrict__ X, const float* __restrict__ bw) {
    int j = blockIdx.x * blockDim.x + threadIdx.x;
    if (j >= NPAD) return;
    float b = bw[0];
    float L = 1.4426950408889634f / (b * b);
    float4* q = (float4*)(g_B + (size_t)j * DD);
    if (j < N_COLS) {
        const float4* p = (const float4*)(X + (size_t)j * DD);
        float s = 0.f;
        #pragma unroll
        for (int t = 0; t < DD / 4; t++) {
            float4 v = p[t];
            s += v.x * v.x + v.y * v.y + v.z * v.z + v.w * v.w;
            float4 o;
            o.x = tf32r(v.x); o.y = tf32r(v.y);
            o.z = tf32r(v.z); o.w = tf32r(v.w);
            q[t] = o;
        }
        g_bx[j] = -0.5f * L * s;
    } else {
        #pragma unroll
        for (int t = 0; t < DD / 4; t++) q[t] = make_float4(0.f, 0.f, 0.f, 0.f);
        g_bx[j] = -1e30f;   // exp2 -> 0 for padded columns
    }
}

// ---------------------------------------------------------------------------
// Main: CTA = 128x128 output tile, K=64 resident. 8 warps (2m x 4n),
// warp tile 64x32 via mma.sync.m16n8k8 tf32. Epilogue: exp2 from fragment
// registers, quad-shuffle + smem reduce -> deterministic partials.
// ---------------------------------------------------------------------------
__global__ void __launch_bounds__(256, 2) gkd_main() {
    extern __shared__ float smem[];
    float* As  = smem;                 // 128*68
    float* Bs  = smem + CTA_M * SA;    // 128*68
    float* bxs = smem + 2 * CTA_M * SA;

    const int nt  = blockIdx.x;        // 0..390
    const int mt  = blockIdx.y;        // 0..31
    const int tid = threadIdx.x;

    // ---- load tiles (coalesced float4, padded smem rows stay 16B aligned) ----
    const float4* gA = (const float4*)(g_A + (size_t)mt * CTA_M * DD);
    const float4* gB = (const float4*)(g_B + (size_t)nt * CTA_N * DD);
    #pragma unroll
    for (int q = 0; q < 8; q++) {
        int e   = tid + q * 256;       // 2048 float4 per tile
        int row = e >> 4;
        int c4  = e & 15;
        *(float4*)(As + row * SA + c4 * 4) = gA[e];
        *(float4*)(Bs + row * SA + c4 * 4) = gB[e];
    }
    if (tid < CTA_N) bxs[tid] = g_bx[(size_t)nt * CTA_N + tid];
    __syncthreads();

    const int lane = tid & 31, wid = tid >> 5;
    const int wm = wid & 1;            // 2 m-halves of 64
    const int wn = wid >> 1;           // 4 n-quarters of 32
    const int r  = lane >> 2;          // row group 0..7
    const int cl = lane & 3;           // k/col sub-lane

    const uint32_t* Au = (const uint32_t*)As + (wm * 64 + r) * SA + cl;
    const uint32_t* Bu = (const uint32_t*)Bs + (wn * 32 + r) * SA + cl;

    float acc[4][4][4];
    #pragma unroll
    for (int mi = 0; mi < 4; mi++)
        #pragma unroll
        for (int ni = 0; ni < 4; ni++)
            #pragma unroll
            for (int e = 0; e < 4; e++) acc[mi][ni][e] = 0.f;

    #pragma unroll
    for (int ks = 0; ks < 8; ks++) {
        const int kb = ks * 8;
        uint32_t a[4][4], b[4][2];
        #pragma unroll
        for (int mi = 0; mi < 4; mi++) {
            const uint32_t* p = Au + mi * 16 * SA + kb;
            a[mi][0] = p[0];          // (row r,    k cl)
            a[mi][1] = p[8 * SA];     // (row r+8,  k cl)
            a[mi][2] = p[4];          // (row r,    k cl+4)
            a[mi][3] = p[8 * SA + 4]; // (row r+8,  k cl+4)
        }
        #pragma unroll
        for (int ni = 0; ni < 4; ni++) {
            const uint32_t* p = Bu + ni * 8 * SA + kb;
            b[ni][0] = p[0];          // (n r, k cl)
            b[ni][1] = p[4];          // (n r, k cl+4)
        }
        #pragma unroll
        for (int mi = 0; mi < 4; mi++)
            #pragma unroll
            for (int ni = 0; ni < 4; ni++)
                mma_tf32(acc[mi][ni], a[mi], b[ni]);
    }
    __syncthreads();   // all warps done reading As/Bs (As reused below)

    // ---- epilogue: exp2(acc + bx) and row sums ----
    float bxv[4][2];
    #pragma unroll
    for (int ni = 0; ni < 4; ni++) {
        int c0 = wn * 32 + ni * 8 + 2 * cl;
        bxv[ni][0] = bxs[c0];
        bxv[ni][1] = bxs[c0 + 1];
    }

    float* red = As;   // 4 n-warps x 128 rows
    #pragma unroll
    for (int mi = 0; mi < 4; mi++) {
        float s0 = 0.f, s1 = 0.f;
        #pragma unroll
        for (int ni = 0; ni < 4; ni++) {
            s0 += fexp2(acc[mi][ni][0] + bxv[ni][0]) + fexp2(acc[mi][ni][1] + bxv[ni][1]);
            s1 += fexp2(acc[mi][ni][2] + bxv[ni][0]) + fexp2(acc[mi][ni][3] + bxv[ni][1]);
        }
        s0 += __shfl_xor_sync(0xffffffffu, s0, 1);
        s0 += __shfl_xor_sync(0xffffffffu, s0, 2);
        s1 += __shfl_xor_sync(0xffffffffu, s1, 1);
        s1 += __shfl_xor_sync(0xffffffffu, s1, 2);
        if (cl == 0) {
            int rl = wm * 64 + mi * 16 + r;        // 0..127 local row
            red[wn * CTA_M + rl]     = s0;
            red[wn * CTA_M + rl + 8] = s1;
        }
    }
    __syncthreads();

    if (tid < CTA_M) {
        float s = red[tid] + red[CTA_M + tid] + red[2 * CTA_M + tid] + red[3 * CTA_M + tid];
        g_part[(size_t)nt * M_ROWS + (size_t)mt * CTA_M + tid] = s;
    }
}

// ---------------------------------------------------------------------------
// Finalize: deterministic fixed-order reduction + log
// ---------------------------------------------------------------------------
__global__ void gkd_finalize(float* __restrict__ out) {
    int i = blockIdx.x * blockDim.x + threadIdx.x;
    if (i >= M_ROWS) return;
    float s = 0.f;
    #pragma unroll 4
    for (int t = 0; t < N_NT; t++)
        s += g_part[(size_t)t * M_ROWS + i];
    // coeff = -(ln(50000) + 32*ln(2*pi)) = -69.63184440950933
    out[i] = 0.6931471805599453f * (g_ax[i] + log2f(s)) - 69.63184440950933f;
}

extern "C" void kernel_launch(void* const* d_in, const int* in_sizes, int n_in,
                              void* d_out, int out_size) {
    const float* x = nullptr; const float* X = nullptr; const float* bw = nullptr;
    for (int i = 0; i < n_in; i++) {
        if (in_sizes[i] == M_ROWS * DD)      x  = (const float*)d_in[i];
        else if (in_sizes[i] == N_COLS * DD) X  = (const float*)d_in[i];
        else if (in_sizes[i] == 1)           bw = (const float*)d_in[i];
    }
    float* out = (float*)d_out;

    const int smem_bytes = (2 * CTA_M * SA + CTA_N) * 4;   // 70144
    cudaFuncSetAttribute(gkd_main, cudaFuncAttributeMaxDynamicSharedMemorySize, smem_bytes);

    gkd_prep_x<<<(M_ROWS + 127) / 128, 128>>>(x, bw);
    gkd_prep_X<<<(NPAD + 127) / 128, 128>>>(X, bw);

    dim3 grid(N_NT, M_ROWS / CTA_M);   // 391 x 32
    gkd_main<<<grid, 256, smem_bytes>>>();

    gkd_finalize<<<(M_ROWS + 255) / 256, 256>>>(out);
}